// round 14
// baseline (speedup 1.0000x reference)
#include <cuda_runtime.h>
#include <cuda_fp16.h>
#include <cstdint>

// ---------------- problem sizes ----------------
#define SZ_M 8192   // 4 * 2048 rows of x
#define SZ_N 4096   // out features
#define SZ_K 4096   // in features

// ---------------- GEMM tiling ----------------
#define BM 128
#define BN 256                 // 2 groups x 128 cols
#define BK 64                  // halves per stage = 128B rows (one SW128 plane)
#define NSTAGE 3
#define KIT (SZ_K / BK)        // 64 k-iterations per tile
#define NTHREADS 256           // 2 groups x 128 threads (4 warps each)

#define NTILE_N (SZ_N / BN)    // 16
#define NTILE_M (SZ_M / BM)    // 64
#define NTILES  (NTILE_N * NTILE_M)   // 1024
#define GRID    148            // persistent: one CTA per SM
#define NGROUPS (GRID * 2)     // 296

// per-group per-stage: A copy 128x128B (16K) + B half 128x128B (16K)
#define GROUP_A_BYTES (BM * 128)               // 16384
#define GROUP_B_BYTES (128 * 128)              // 16384
#define GROUP_BYTES   (GROUP_A_BYTES + GROUP_B_BYTES)   // 32768
#define STAGE_BYTES   (2 * GROUP_BYTES)                 // 65536
#define SMEM_TOTAL    (NSTAGE * STAGE_BYTES)            // 196608

// conversion layout: 64 x-chunks of 128 rows; first XUP upfront, rest lazy
#define NXCHUNK   64
#define XUP       16
#define F4_CHUNK  (128 * SZ_K / 4)        // 131072 float4 per chunk
#define STRIPE_F4 443                      // ceil(131072 / 296)
#define W_INT4    ((size_t)SZ_N * SZ_K / 4)   // 4194304
#define XUP_F4    ((size_t)XUP * F4_CHUNK)    // 2097152

static_assert(SZ_M % BM == 0 && SZ_N % BN == 0 && SZ_K % BK == 0, "tiling");

// ---------------- scratch (no cudaMalloc allowed) ----------------
__device__ __align__(16) __half g_xh[(size_t)SZ_M * SZ_K];   // 64 MB
__device__ __align__(16) __half g_wh[(size_t)SZ_N * SZ_K];   // 32 MB
__device__ unsigned long long g_ticket;                      // phase-A barrier
__device__ int g_cnt[NXCHUNK];                               // lazy-chunk arrivals

// ---------------- helpers ----------------
static __device__ __forceinline__ uint32_t smem_u32(const void* p) {
    uint32_t r;
    asm("{ .reg .u64 t; cvta.to.shared.u64 t, %1; cvt.u32.u64 %0, t; }"
        : "=r"(r) : "l"(p));
    return r;
}

static __device__ __forceinline__ void cp16(uint32_t dst, const void* src) {
    asm volatile("cp.async.cg.shared.global [%0], [%1], 16;"
                 :: "r"(dst), "l"(src) : "memory");
}

static __device__ __forceinline__ uint32_t sw128(uint32_t off) {
    return off ^ ((off >> 3) & 0x70);
}

static __device__ __forceinline__ void ldm_x4(uint32_t addr,
    uint32_t& r0, uint32_t& r1, uint32_t& r2, uint32_t& r3) {
    asm volatile("ldmatrix.sync.aligned.m8n8.x4.shared.b16 {%0,%1,%2,%3}, [%4];"
                 : "=r"(r0), "=r"(r1), "=r"(r2), "=r"(r3) : "r"(addr));
}

static __device__ __forceinline__ void mma16816(
    float& d0, float& d1, float& d2, float& d3,
    uint32_t a0, uint32_t a1, uint32_t a2, uint32_t a3,
    uint32_t b0, uint32_t b1) {
    asm volatile(
        "mma.sync.aligned.m16n8k16.row.col.f32.f16.f16.f32 "
        "{%0,%1,%2,%3}, {%4,%5,%6,%7}, {%8,%9}, {%0,%1,%2,%3};"
        : "+f"(d0), "+f"(d1), "+f"(d2), "+f"(d3)
        : "r"(a0), "r"(a1), "r"(a2), "r"(a3), "r"(b0), "r"(b1));
}

// group-scoped named barrier (128 threads)
static __device__ __forceinline__ void group_bar(int g) {
    asm volatile("bar.sync %0, 128;" :: "r"(g + 1) : "memory");
}

// ---------------- per-group stage loader (128 threads of group g) ----------------
static __device__ __forceinline__ void load_stage(
    uint32_t sb, int s, int m0, int n0, int kt, int g, int gtid)
{
    const uint32_t base = sb + (uint32_t)s * STAGE_BYTES + (uint32_t)g * GROUP_BYTES;
    const int kh = kt * BK;

    // A: own copy of the full 128-row A tile (8 chunks/thread)
    #pragma unroll
    for (int i = 0; i < (BM * 8) / 128; i++) {
        int c = gtid + i * 128;
        int row = c >> 3, seg = c & 7;
        uint32_t off = (uint32_t)row * 128 + (uint32_t)seg * 16;
        cp16(base + sw128(off), g_xh + (size_t)(m0 + row) * SZ_K + kh + seg * 8);
    }
    // B half: group's 128 columns (8 chunks/thread)
    const uint32_t bbase = base + GROUP_A_BYTES;
    const int bn0 = n0 + g * 128;
    #pragma unroll
    for (int i = 0; i < (128 * 8) / 128; i++) {
        int c = gtid + i * 128;
        int row = c >> 3, seg = c & 7;
        uint32_t off = (uint32_t)row * 128 + (uint32_t)seg * 16;
        cp16(bbase + sw128(off), g_wh + (size_t)(bn0 + row) * SZ_K + kh + seg * 8);
    }
}

// ---------------- fused persistent kernel ----------------
// Phase A: ALL 148 CTAs cooperatively (grid-strided, full-chip DRAM bandwidth)
// convert W and the first XUP x-chunks, then a global ticket barrier.
// Phase B: R12 GEMM mainloop; remaining x-chunks are converted lazily inside
// the j-loop (1 float4/thread/iter, LDG hoisted before the ks-loop, store sunk
// after), published per-group via monotonic counters; consumers spin only at
// tile entry. All sync objects are monotonic -> graph-replay safe.
__global__ void __launch_bounds__(NTHREADS, 1)
gemm_hmma_kernel(const float* __restrict__ gx,
                 const int* __restrict__ qw,
                 const float* __restrict__ wscale,
                 const float* __restrict__ bias,
                 float* __restrict__ out)
{
    extern __shared__ char smem[];
    __shared__ int s_callk;
    const uint32_t sb = smem_u32(smem);
    const int tid  = threadIdx.x;
    const int wid  = tid >> 5;
    const int lane = tid & 31;
    const int g    = wid >> 2;        // group 0/1
    const int w    = wid & 3;
    const int wm   = w & 1;
    const int wn   = w >> 1;
    const int gtid = tid & 127;
    const int bid  = blockIdx.x;

    // ================= Phase A: cooperative convert + global barrier ========
    {
        const int4* wsrc = reinterpret_cast<const int4*>(qw);
        uint2* wdst = reinterpret_cast<uint2*>(g_wh);
        for (size_t i = (size_t)bid * NTHREADS + tid; i < W_INT4;
             i += (size_t)GRID * NTHREADS) {
            int4 v = __ldg(wsrc + i);
            __half2 h0 = __halves2half2(__int2half_rn(v.x), __int2half_rn(v.y));
            __half2 h1 = __halves2half2(__int2half_rn(v.z), __int2half_rn(v.w));
            uint2 r;
            r.x = *reinterpret_cast<unsigned*>(&h0);
            r.y = *reinterpret_cast<unsigned*>(&h1);
            wdst[i] = r;
        }
        const float4* xsrc = reinterpret_cast<const float4*>(gx);
        uint2* xdst = reinterpret_cast<uint2*>(g_xh);
        for (size_t i = (size_t)bid * NTHREADS + tid; i < XUP_F4;
             i += (size_t)GRID * NTHREADS) {
            float4 v = __ldg(xsrc + i);
            __half2 h0 = __floats2half2_rn(v.x, v.y);
            __half2 h1 = __floats2half2_rn(v.z, v.w);
            uint2 r;
            r.x = *reinterpret_cast<unsigned*>(&h0);
            r.y = *reinterpret_cast<unsigned*>(&h1);
            xdst[i] = r;
        }
        __threadfence();
        __syncthreads();
        if (tid == 0) {
            unsigned long long t = atomicAdd(&g_ticket, 1ULL);
            int k = (int)(t / (unsigned long long)GRID);
            s_callk = k;
            unsigned long long tgt = (unsigned long long)(k + 1) * GRID;
            while (*(volatile unsigned long long*)&g_ticket < tgt) __nanosleep(128);
        }
        __syncthreads();
    }
    const int cnt_tgt = NGROUPS * (s_callk + 1);
    asm volatile("fence.proxy.async;" ::: "memory");

    // ================= Phase B: GEMM with lazy x conversion ==================
    const int ntiles = (NTILES - 1 - bid) / GRID + 1;
    const int GJ = ntiles * KIT;

    const int l7   = lane & 7;
    const int hi8  = (lane >> 3) & 1;
    const int hi16 = lane >> 4;

    const int arow_base = wm * 64 + hi8 * 8 + l7;
    const int akb_base  = hi16 * 16;
    const int brow_base = wn * 64 + hi16 * 8 + l7;
    const int bkb_base  = hi8 * 16;

    float d[4][8][4];
    #pragma unroll
    for (int i = 0; i < 4; i++)
        #pragma unroll
        for (int j = 0; j < 8; j++)
            #pragma unroll
            for (int c = 0; c < 4; c++) d[i][j][c] = 0.0f;

    // lazy-conversion duty state (per thread; stripe owned by group gg)
    const int gg = bid * 2 + g;               // 0..295
    int cc = XUP;                              // next chunk to convert
    int cstep = 0;                             // 0..3 within stripe
    int pending = -1;                          // chunk awaiting publish

    // incremental coordinates of the tile being LOADED (j+2 stream)
    int lt  = bid;
    int lkt = 0;
    int ln0 = (lt & (NTILE_N - 1)) * BN;
    int lm0 = (lt >> 4) * BM;

    // prologue (tile bid uses x chunks <= 9: all upfront)
    load_stage(sb, 0, lm0, ln0, 0, g, gtid);
    asm volatile("cp.async.commit_group;" ::: "memory");
    load_stage(sb, 1, lm0, ln0, 1, g, gtid);
    asm volatile("cp.async.commit_group;" ::: "memory");
    lkt = 2;

    int et  = bid;
    int en0 = ln0, em0 = lm0;

    int s0 = 0;   // stage of j
    int s2 = 2;   // stage of j+2

    #pragma unroll 1
    for (int j = 0; j < GJ; j++) {
        if (j + 2 < GJ)
            asm volatile("cp.async.wait_group 1;" ::: "memory");
        else
            asm volatile("cp.async.wait_group 0;" ::: "memory");
        group_bar(g);   // stage j resident for this group

        // publish chunk finished last iter (stores fenced before the bar above)
        if (pending >= 0) {
            if (gtid == 0) atomicAdd(&g_cnt[pending], 1);
            pending = -1;
        }

        if (j + 2 < GJ) {
            if (lkt == 0) {   // entering a new tile: ensure its x chunk is ready
                const int xc = lm0 >> 7;
                if (xc >= XUP) {
                    volatile int* c = &g_cnt[xc];
                    while (*c < cnt_tgt) __nanosleep(64);
                    asm volatile("fence.proxy.async;" ::: "memory");
                }
            }
            load_stage(sb, s2, lm0, ln0, lkt, g, gtid);
            asm volatile("cp.async.commit_group;" ::: "memory");
            if (++lkt == KIT) {
                lkt = 0;
                lt += GRID;
                ln0 = (lt & (NTILE_N - 1)) * BN;
                lm0 = (lt >> 4) * BM;
            }
        }

        // conversion duty: issue LDG now, convert/store after the ks loop
        float4 cv;
        bool cvalid = false;
        int cidx = 0;
        if (cc < NXCHUNK) {
            const int e = cstep * 128 + gtid;
            const int sbeg = gg * STRIPE_F4;
            cvalid = (e < STRIPE_F4) && (sbeg + e < F4_CHUNK);
            cidx = cc * F4_CHUNK + sbeg + e;
            if (cvalid) cv = __ldg(reinterpret_cast<const float4*>(gx) + cidx);
        }

        const uint32_t abase = sb + (uint32_t)s0 * STAGE_BYTES + (uint32_t)g * GROUP_BYTES;
        const uint32_t bbase = abase + GROUP_A_BYTES;

        #pragma unroll
        for (int ks = 0; ks < BK / 16; ks++) {
            uint32_t a[4][4];
            #pragma unroll
            for (int mt = 0; mt < 4; mt++) {
                uint32_t off = (uint32_t)(arow_base + mt * 16) * 128
                             + (uint32_t)(ks * 32 + akb_base);
                ldm_x4(abase + sw128(off), a[mt][0], a[mt][1], a[mt][2], a[mt][3]);
            }
            uint32_t bfr[8][2];
            #pragma unroll
            for (int np = 0; np < 4; np++) {
                uint32_t off = (uint32_t)(brow_base + np * 16) * 128
                             + (uint32_t)(ks * 32 + bkb_base);
                uint32_t r0, r1, r2, r3;
                ldm_x4(bbase + sw128(off), r0, r1, r2, r3);
                bfr[np * 2 + 0][0] = r0; bfr[np * 2 + 0][1] = r1;
                bfr[np * 2 + 1][0] = r2; bfr[np * 2 + 1][1] = r3;
            }
            #pragma unroll
            for (int mt = 0; mt < 4; mt++)
                #pragma unroll
                for (int nt = 0; nt < 8; nt++)
                    mma16816(d[mt][nt][0], d[mt][nt][1], d[mt][nt][2], d[mt][nt][3],
                             a[mt][0], a[mt][1], a[mt][2], a[mt][3],
                             bfr[nt][0], bfr[nt][1]);
        }

        // complete conversion duty for this iter
        if (cc < NXCHUNK) {
            if (cvalid) {
                __half2 h0 = __floats2half2_rn(cv.x, cv.y);
                __half2 h1 = __floats2half2_rn(cv.z, cv.w);
                uint2 r;
                r.x = *reinterpret_cast<unsigned*>(&h0);
                r.y = *reinterpret_cast<unsigned*>(&h1);
                reinterpret_cast<uint2*>(g_xh)[cidx] = r;
            }
            if (++cstep == 4) {
                cstep = 0;
                __threadfence();   // stores visible before next-iter publish
                pending = cc;
                cc++;
            }
        }

        s0 = (s0 == 2) ? 0 : s0 + 1;
        s2 = (s2 == 2) ? 0 : s2 + 1;

        // ---------------- tile epilogue ----------------
        if ((j & (KIT - 1)) == KIT - 1) {
            const int crow = em0 + wm * 64 + (lane >> 2);
            const int ccol = en0 + g * 128 + wn * 64 + (lane & 3) * 2;

            float sc0[8], sc1[8], bi0[8], bi1[8];
            #pragma unroll
            for (int nt = 0; nt < 8; nt++) {
                sc0[nt] = __ldg(wscale + ccol + nt * 8);
                sc1[nt] = __ldg(wscale + ccol + nt * 8 + 1);
                bi0[nt] = __ldg(bias   + ccol + nt * 8);
                bi1[nt] = __ldg(bias   + ccol + nt * 8 + 1);
            }

            #pragma unroll
            for (int mt = 0; mt < 4; mt++) {
                #pragma unroll
                for (int nt = 0; nt < 8; nt++) {
                    float2 v0, v1;
                    v0.x = fmaf(d[mt][nt][0], sc0[nt], bi0[nt]);
                    v0.y = fmaf(d[mt][nt][1], sc1[nt], bi1[nt]);
                    v1.x = fmaf(d[mt][nt][2], sc0[nt], bi0[nt]);
                    v1.y = fmaf(d[mt][nt][3], sc1[nt], bi1[nt]);
                    size_t r0 = (size_t)(crow + mt * 16) * SZ_N + ccol + nt * 8;
                    size_t r1 = r0 + 8 * SZ_N;
                    *reinterpret_cast<float2*>(out + r0) = v0;
                    *reinterpret_cast<float2*>(out + r1) = v1;
                    d[mt][nt][0] = 0.0f; d[mt][nt][1] = 0.0f;
                    d[mt][nt][2] = 0.0f; d[mt][nt][3] = 0.0f;
                }
            }

            et += GRID;
            en0 = (et & (NTILE_N - 1)) * BN;
            em0 = (et >> 4) * BM;
        }
    }
}

// ---------------- launch ----------------
extern "C" void kernel_launch(void* const* d_in, const int* in_sizes, int n_in,
                              void* d_out, int out_size)
{
    const float* x  = (const float*)d_in[0];   // [4,2048,4096] fp32
    const int*   qw = (const int*)  d_in[1];   // [4096,4096] int32 in [-8,7]
    const float* ws = (const float*)d_in[2];   // [4096]
    const float* bs = (const float*)d_in[3];   // [4096]
    float* out = (float*)d_out;                // [4,2048,4096] fp32

    cudaFuncSetAttribute(gemm_hmma_kernel,
                         cudaFuncAttributeMaxDynamicSharedMemorySize, SMEM_TOTAL);

    gemm_hmma_kernel<<<GRID, NTHREADS, SMEM_TOTAL>>>(x, qw, ws, bs, out);
}

// round 15
// speedup vs baseline: 1.4783x; 1.4783x over previous
#include <cuda_runtime.h>
#include <cuda_fp16.h>
#include <cstdint>

// ---------------- problem sizes ----------------
#define SZ_M 8192   // 4 * 2048 rows of x
#define SZ_N 4096   // out features
#define SZ_K 4096   // in features

// ---------------- GEMM tiling ----------------
#define BM 128
#define BN 256                 // 2 groups x 128 cols
#define BK 64                  // halves per stage = 128B rows (one SW128 plane)
#define NSTAGE 3
#define KIT (SZ_K / BK)        // 64 k-iterations per tile
#define NTHREADS 256           // 2 groups x 128 threads (4 warps each)

#define NTILE_N (SZ_N / BN)    // 16
#define NTILE_M (SZ_M / BM)    // 64
#define NTILES  (NTILE_N * NTILE_M)   // 1024
#define GRID    148            // persistent: one CTA per SM

// per-group per-stage: A copy 128x128B (16K) + B half 128x128B (16K)
#define GROUP_A_BYTES (BM * 128)               // 16384
#define GROUP_B_BYTES (128 * 128)              // 16384
#define GROUP_BYTES   (GROUP_A_BYTES + GROUP_B_BYTES)   // 32768
#define STAGE_BYTES   (2 * GROUP_BYTES)                 // 65536
#define SMEM_TOTAL    (NSTAGE * STAGE_BYTES)            // 196608

static_assert(SZ_M % BM == 0 && SZ_N % BN == 0 && SZ_K % BK == 0, "tiling");

// ---------------- scratch (no cudaMalloc allowed) ----------------
__device__ __align__(16) __half g_xh[(size_t)SZ_M * SZ_K];   // 64 MB
__device__ __align__(16) __half g_wh[(size_t)SZ_N * SZ_K];   // 32 MB

// ---------------- helpers ----------------
static __device__ __forceinline__ uint32_t smem_u32(const void* p) {
    uint32_t r;
    asm("{ .reg .u64 t; cvta.to.shared.u64 t, %1; cvt.u32.u64 %0, t; }"
        : "=r"(r) : "l"(p));
    return r;
}

static __device__ __forceinline__ void cp16(uint32_t dst, const void* src) {
    asm volatile("cp.async.cg.shared.global [%0], [%1], 16;"
                 :: "r"(dst), "l"(src) : "memory");
}

static __device__ __forceinline__ uint32_t sw128(uint32_t off) {
    return off ^ ((off >> 3) & 0x70);
}

static __device__ __forceinline__ void ldm_x4(uint32_t addr,
    uint32_t& r0, uint32_t& r1, uint32_t& r2, uint32_t& r3) {
    asm volatile("ldmatrix.sync.aligned.m8n8.x4.shared.b16 {%0,%1,%2,%3}, [%4];"
                 : "=r"(r0), "=r"(r1), "=r"(r2), "=r"(r3) : "r"(addr));
}

static __device__ __forceinline__ void mma16816(
    float& d0, float& d1, float& d2, float& d3,
    uint32_t a0, uint32_t a1, uint32_t a2, uint32_t a3,
    uint32_t b0, uint32_t b1) {
    asm volatile(
        "mma.sync.aligned.m16n8k16.row.col.f32.f16.f16.f32 "
        "{%0,%1,%2,%3}, {%4,%5,%6,%7}, {%8,%9}, {%0,%1,%2,%3};"
        : "+f"(d0), "+f"(d1), "+f"(d2), "+f"(d3)
        : "r"(a0), "r"(a1), "r"(a2), "r"(a3), "r"(b0), "r"(b1));
}

// group-scoped named barrier (128 threads)
static __device__ __forceinline__ void group_bar(int g) {
    asm volatile("bar.sync %0, 128;" :: "r"(g + 1) : "memory");
}

// ---------------- fused convert kernel (wide: 8 elems/thread) ----------------
// x: 2x float4 load -> 1x uint4 store. w: 2x int4 load -> 1x uint4 store.
// Doubled per-thread MLP + 16B stores push the streaming kernel toward the
// DRAM ceiling (R2 profile showed 70% with the narrow version).
#define XC8 ((size_t)SZ_M * SZ_K / 8)
#define WC8 ((size_t)SZ_N * SZ_K / 8)

__global__ void __launch_bounds__(256) cvt_all_kernel(
    const float* __restrict__ x, const int* __restrict__ q)
{
    size_t i = (size_t)blockIdx.x * blockDim.x + threadIdx.x;
    if (i < XC8) {
        const float4* src = reinterpret_cast<const float4*>(x) + i * 2;
        float4 v0 = __ldg(src);
        float4 v1 = __ldg(src + 1);
        __half2 h0 = __floats2half2_rn(v0.x, v0.y);
        __half2 h1 = __floats2half2_rn(v0.z, v0.w);
        __half2 h2 = __floats2half2_rn(v1.x, v1.y);
        __half2 h3 = __floats2half2_rn(v1.z, v1.w);
        uint4 r;
        r.x = *reinterpret_cast<unsigned*>(&h0);
        r.y = *reinterpret_cast<unsigned*>(&h1);
        r.z = *reinterpret_cast<unsigned*>(&h2);
        r.w = *reinterpret_cast<unsigned*>(&h3);
        reinterpret_cast<uint4*>(g_xh)[i] = r;
    } else {
        size_t j = i - XC8;
        const int4* src = reinterpret_cast<const int4*>(q) + j * 2;
        int4 v0 = __ldg(src);
        int4 v1 = __ldg(src + 1);
        __half2 h0 = __halves2half2(__int2half_rn(v0.x), __int2half_rn(v0.y));
        __half2 h1 = __halves2half2(__int2half_rn(v0.z), __int2half_rn(v0.w));
        __half2 h2 = __halves2half2(__int2half_rn(v1.x), __int2half_rn(v1.y));
        __half2 h3 = __halves2half2(__int2half_rn(v1.z), __int2half_rn(v1.w));
        uint4 r;
        r.x = *reinterpret_cast<unsigned*>(&h0);
        r.y = *reinterpret_cast<unsigned*>(&h1);
        r.z = *reinterpret_cast<unsigned*>(&h2);
        r.w = *reinterpret_cast<unsigned*>(&h3);
        reinterpret_cast<uint4*>(g_wh)[j] = r;
    }
}

// ---------------- per-group stage loader (128 threads of group g) ----------------
static __device__ __forceinline__ void load_stage(
    uint32_t sb, int s, int m0, int n0, int kt, int g, int gtid)
{
    const uint32_t base = sb + (uint32_t)s * STAGE_BYTES + (uint32_t)g * GROUP_BYTES;
    const int kh = kt * BK;

    // A: own copy of the full 128-row A tile (8 chunks/thread)
    #pragma unroll
    for (int i = 0; i < (BM * 8) / 128; i++) {
        int c = gtid + i * 128;
        int row = c >> 3, seg = c & 7;
        uint32_t off = (uint32_t)row * 128 + (uint32_t)seg * 16;
        cp16(base + sw128(off), g_xh + (size_t)(m0 + row) * SZ_K + kh + seg * 8);
    }
    // B half: group's 128 columns (8 chunks/thread)
    const uint32_t bbase = base + GROUP_A_BYTES;
    const int bn0 = n0 + g * 128;
    #pragma unroll
    for (int i = 0; i < (128 * 8) / 128; i++) {
        int c = gtid + i * 128;
        int row = c >> 3, seg = c & 7;
        uint32_t off = (uint32_t)row * 128 + (uint32_t)seg * 16;
        cp16(bbase + sw128(off), g_wh + (size_t)(bn0 + row) * SZ_K + kh + seg * 8);
    }
}

// ---------------- persistent GEMM kernel (R12 winner, unchanged) ----------------
// 148 persistent CTAs, 2 decorrelated 128-thread groups with named barriers,
// cp.async pipeline linearized across tile boundaries, incremental coordinates,
// hoisted epilogue scale/bias loads.
__global__ void __launch_bounds__(NTHREADS, 1)
gemm_hmma_kernel(const float* __restrict__ wscale,
                 const float* __restrict__ bias,
                 float* __restrict__ out)
{
    extern __shared__ char smem[];
    const uint32_t sb = smem_u32(smem);
    const int tid  = threadIdx.x;
    const int wid  = tid >> 5;
    const int lane = tid & 31;
    const int g    = wid >> 2;        // group 0/1
    const int w    = wid & 3;
    const int wm   = w & 1;
    const int wn   = w >> 1;
    const int gtid = tid & 127;
    const int bid  = blockIdx.x;

    const int ntiles = (NTILES - 1 - bid) / GRID + 1;
    const int GJ = ntiles * KIT;

    const int l7   = lane & 7;
    const int hi8  = (lane >> 3) & 1;
    const int hi16 = lane >> 4;

    const int arow_base = wm * 64 + hi8 * 8 + l7;
    const int akb_base  = hi16 * 16;
    const int brow_base = wn * 64 + hi16 * 8 + l7;
    const int bkb_base  = hi8 * 16;

    float d[4][8][4];
    #pragma unroll
    for (int i = 0; i < 4; i++)
        #pragma unroll
        for (int j = 0; j < 8; j++)
            #pragma unroll
            for (int c = 0; c < 4; c++) d[i][j][c] = 0.0f;

    // incremental coordinates of the tile being LOADED (j+2 stream)
    int lt  = bid;
    int lkt = 0;
    int ln0 = (lt & (NTILE_N - 1)) * BN;
    int lm0 = (lt >> 4) * BM;

    load_stage(sb, 0, lm0, ln0, 0, g, gtid);
    asm volatile("cp.async.commit_group;" ::: "memory");
    load_stage(sb, 1, lm0, ln0, 1, g, gtid);
    asm volatile("cp.async.commit_group;" ::: "memory");
    lkt = 2;

    // incremental coordinates of the tile being COMPUTED / epilogued
    int et  = bid;
    int en0 = ln0, em0 = lm0;

    int s0 = 0;   // stage of j
    int s2 = 2;   // stage of j+2

    #pragma unroll 1
    for (int j = 0; j < GJ; j++) {
        if (j + 2 < GJ)
            asm volatile("cp.async.wait_group 1;" ::: "memory");
        else
            asm volatile("cp.async.wait_group 0;" ::: "memory");
        group_bar(g);   // stage j resident for this group

        if (j + 2 < GJ) {
            load_stage(sb, s2, lm0, ln0, lkt, g, gtid);
            asm volatile("cp.async.commit_group;" ::: "memory");
            if (++lkt == KIT) {
                lkt = 0;
                lt += GRID;
                ln0 = (lt & (NTILE_N - 1)) * BN;
                lm0 = (lt >> 4) * BM;
            }
        }

        const uint32_t abase = sb + (uint32_t)s0 * STAGE_BYTES + (uint32_t)g * GROUP_BYTES;
        const uint32_t bbase = abase + GROUP_A_BYTES;

        #pragma unroll
        for (int ks = 0; ks < BK / 16; ks++) {
            uint32_t a[4][4];
            #pragma unroll
            for (int mt = 0; mt < 4; mt++) {
                uint32_t off = (uint32_t)(arow_base + mt * 16) * 128
                             + (uint32_t)(ks * 32 + akb_base);
                ldm_x4(abase + sw128(off), a[mt][0], a[mt][1], a[mt][2], a[mt][3]);
            }
            uint32_t bfr[8][2];
            #pragma unroll
            for (int np = 0; np < 4; np++) {
                uint32_t off = (uint32_t)(brow_base + np * 16) * 128
                             + (uint32_t)(ks * 32 + bkb_base);
                uint32_t r0, r1, r2, r3;
                ldm_x4(bbase + sw128(off), r0, r1, r2, r3);
                bfr[np * 2 + 0][0] = r0; bfr[np * 2 + 0][1] = r1;
                bfr[np * 2 + 1][0] = r2; bfr[np * 2 + 1][1] = r3;
            }
            #pragma unroll
            for (int mt = 0; mt < 4; mt++)
                #pragma unroll
                for (int nt = 0; nt < 8; nt++)
                    mma16816(d[mt][nt][0], d[mt][nt][1], d[mt][nt][2], d[mt][nt][3],
                             a[mt][0], a[mt][1], a[mt][2], a[mt][3],
                             bfr[nt][0], bfr[nt][1]);
        }

        s0 = (s0 == 2) ? 0 : s0 + 1;
        s2 = (s2 == 2) ? 0 : s2 + 1;

        // ---------------- tile epilogue ----------------
        if ((j & (KIT - 1)) == KIT - 1) {
            const int crow = em0 + wm * 64 + (lane >> 2);
            const int ccol = en0 + g * 128 + wn * 64 + (lane & 3) * 2;

            float sc0[8], sc1[8], bi0[8], bi1[8];
            #pragma unroll
            for (int nt = 0; nt < 8; nt++) {
                sc0[nt] = __ldg(wscale + ccol + nt * 8);
                sc1[nt] = __ldg(wscale + ccol + nt * 8 + 1);
                bi0[nt] = __ldg(bias   + ccol + nt * 8);
                bi1[nt] = __ldg(bias   + ccol + nt * 8 + 1);
            }

            #pragma unroll
            for (int mt = 0; mt < 4; mt++) {
                #pragma unroll
                for (int nt = 0; nt < 8; nt++) {
                    float2 v0, v1;
                    v0.x = fmaf(d[mt][nt][0], sc0[nt], bi0[nt]);
                    v0.y = fmaf(d[mt][nt][1], sc1[nt], bi1[nt]);
                    v1.x = fmaf(d[mt][nt][2], sc0[nt], bi0[nt]);
                    v1.y = fmaf(d[mt][nt][3], sc1[nt], bi1[nt]);
                    size_t r0 = (size_t)(crow + mt * 16) * SZ_N + ccol + nt * 8;
                    size_t r1 = r0 + 8 * SZ_N;
                    *reinterpret_cast<float2*>(out + r0) = v0;
                    *reinterpret_cast<float2*>(out + r1) = v1;
                    d[mt][nt][0] = 0.0f; d[mt][nt][1] = 0.0f;
                    d[mt][nt][2] = 0.0f; d[mt][nt][3] = 0.0f;
                }
            }

            et += GRID;
            en0 = (et & (NTILE_N - 1)) * BN;
            em0 = (et >> 4) * BM;
        }
    }
}

// ---------------- launch ----------------
extern "C" void kernel_launch(void* const* d_in, const int* in_sizes, int n_in,
                              void* d_out, int out_size)
{
    const float* x  = (const float*)d_in[0];   // [4,2048,4096] fp32
    const int*   qw = (const int*)  d_in[1];   // [4096,4096] int32 in [-8,7]
    const float* ws = (const float*)d_in[2];   // [4096]
    const float* bs = (const float*)d_in[3];   // [4096]
    float* out = (float*)d_out;                // [4,2048,4096] fp32

    cudaFuncSetAttribute(gemm_hmma_kernel,
                         cudaFuncAttributeMaxDynamicSharedMemorySize, SMEM_TOTAL);

    cvt_all_kernel<<<(unsigned)((XC8 + WC8) / 256), 256>>>(x, qw);

    gemm_hmma_kernel<<<GRID, NTHREADS, SMEM_TOTAL>>>(ws, bs, out);
}

// round 16
// speedup vs baseline: 1.4868x; 1.0058x over previous
#include <cuda_runtime.h>
#include <cuda_fp16.h>
#include <cstdint>

// ---------------- problem sizes ----------------
#define SZ_M 8192   // 4 * 2048 rows of x
#define SZ_N 4096   // out features
#define SZ_K 4096   // in features

// ---------------- GEMM tiling ----------------
#define BM 128
#define BN 256                 // 2 groups x 128 cols
#define BK 64                  // halves per stage = 128B rows (one SW128 plane)
#define NSTAGE 3
#define KIT (SZ_K / BK)        // 64 k-iterations per tile
#define NTHREADS 256           // 2 groups x 128 threads (4 warps each)

#define NTILE_N (SZ_N / BN)    // 16
#define NTILE_M (SZ_M / BM)    // 64
#define NTILES  (NTILE_N * NTILE_M)   // 1024
#define GRID    148            // persistent: one CTA per SM
#define NTHRG   (GRID * NTHREADS)     // 37888 threads chip-wide

// per-group per-stage: A copy 128x128B (16K) + B half 128x128B (16K)
#define GROUP_A_BYTES (BM * 128)               // 16384
#define GROUP_B_BYTES (128 * 128)              // 16384
#define GROUP_BYTES   (GROUP_A_BYTES + GROUP_B_BYTES)   // 32768
#define STAGE_BYTES   (2 * GROUP_BYTES)                 // 65536
#define SMEM_TILES    (NSTAGE * STAGE_BYTES)            // 196608

// convert-duty staging (gemmA only): 2 buffers x 256 thr x 4 x 16B
#define DUTY         4
#define STAGE_OFF    SMEM_TILES
#define STAGE_BUF    (NTHREADS * DUTY * 16)             // 16384
#define SMEM_TOTAL   (SMEM_TILES + 2 * STAGE_BUF)       // 229376

// conversion layout: x has 64 chunks of 128 rows; chunks 0..9 upfront, 10..63 lazy
#define F4_CHUNK  (128 * SZ_K / 4)            // 131072 float4 per chunk
#define P2BASE    ((size_t)10 * F4_CHUNK)     // first lazy f4
#define P2F4      ((size_t)54 * F4_CHUNK)     // 7077888 lazy f4s
#define X10C8     ((size_t)10 * 128 * SZ_K / 8)   // 655360 wide-convert threads (x)
#define WC8       ((size_t)SZ_N * SZ_K / 8)       // 2097152 (W)

static_assert(SZ_M % BM == 0 && SZ_N % BN == 0 && SZ_K % BK == 0, "tiling");

// ---------------- scratch (no cudaMalloc allowed) ----------------
__device__ __align__(16) __half g_xh[(size_t)SZ_M * SZ_K];   // 64 MB
__device__ __align__(16) __half g_wh[(size_t)SZ_N * SZ_K];   // 32 MB

// ---------------- helpers ----------------
static __device__ __forceinline__ uint32_t smem_u32(const void* p) {
    uint32_t r;
    asm("{ .reg .u64 t; cvta.to.shared.u64 t, %1; cvt.u32.u64 %0, t; }"
        : "=r"(r) : "l"(p));
    return r;
}

static __device__ __forceinline__ void cp16(uint32_t dst, const void* src) {
    asm volatile("cp.async.cg.shared.global [%0], [%1], 16;"
                 :: "r"(dst), "l"(src) : "memory");
}

static __device__ __forceinline__ uint32_t sw128(uint32_t off) {
    return off ^ ((off >> 3) & 0x70);
}

static __device__ __forceinline__ void ldm_x4(uint32_t addr,
    uint32_t& r0, uint32_t& r1, uint32_t& r2, uint32_t& r3) {
    asm volatile("ldmatrix.sync.aligned.m8n8.x4.shared.b16 {%0,%1,%2,%3}, [%4];"
                 : "=r"(r0), "=r"(r1), "=r"(r2), "=r"(r3) : "r"(addr));
}

static __device__ __forceinline__ void mma16816(
    float& d0, float& d1, float& d2, float& d3,
    uint32_t a0, uint32_t a1, uint32_t a2, uint32_t a3,
    uint32_t b0, uint32_t b1) {
    asm volatile(
        "mma.sync.aligned.m16n8k16.row.col.f32.f16.f16.f32 "
        "{%0,%1,%2,%3}, {%4,%5,%6,%7}, {%8,%9}, {%0,%1,%2,%3};"
        : "+f"(d0), "+f"(d1), "+f"(d2), "+f"(d3)
        : "r"(a0), "r"(a1), "r"(a2), "r"(a3), "r"(b0), "r"(b1));
}

// group-scoped named barrier (128 threads)
static __device__ __forceinline__ void group_bar(int g) {
    asm volatile("bar.sync %0, 128;" :: "r"(g + 1) : "memory");
}

// ---------------- phase-1 convert: W (all) + x chunks 0..9, wide ----------------
__global__ void __launch_bounds__(256) cvt_phase1_kernel(
    const float* __restrict__ x, const int* __restrict__ q)
{
    size_t i = (size_t)blockIdx.x * blockDim.x + threadIdx.x;
    if (i < X10C8) {
        const float4* src = reinterpret_cast<const float4*>(x) + i * 2;
        float4 v0 = __ldg(src);
        float4 v1 = __ldg(src + 1);
        __half2 h0 = __floats2half2_rn(v0.x, v0.y);
        __half2 h1 = __floats2half2_rn(v0.z, v0.w);
        __half2 h2 = __floats2half2_rn(v1.x, v1.y);
        __half2 h3 = __floats2half2_rn(v1.z, v1.w);
        uint4 r;
        r.x = *reinterpret_cast<unsigned*>(&h0);
        r.y = *reinterpret_cast<unsigned*>(&h1);
        r.z = *reinterpret_cast<unsigned*>(&h2);
        r.w = *reinterpret_cast<unsigned*>(&h3);
        reinterpret_cast<uint4*>(g_xh)[i] = r;
    } else {
        size_t j = i - X10C8;
        const int4* src = reinterpret_cast<const int4*>(q) + j * 2;
        int4 v0 = __ldg(src);
        int4 v1 = __ldg(src + 1);
        __half2 h0 = __halves2half2(__int2half_rn(v0.x), __int2half_rn(v0.y));
        __half2 h1 = __halves2half2(__int2half_rn(v0.z), __int2half_rn(v0.w));
        __half2 h2 = __halves2half2(__int2half_rn(v1.x), __int2half_rn(v1.y));
        __half2 h3 = __halves2half2(__int2half_rn(v1.z), __int2half_rn(v1.w));
        uint4 r;
        r.x = *reinterpret_cast<unsigned*>(&h0);
        r.y = *reinterpret_cast<unsigned*>(&h1);
        r.z = *reinterpret_cast<unsigned*>(&h2);
        r.w = *reinterpret_cast<unsigned*>(&h3);
        reinterpret_cast<uint4*>(g_wh)[j] = r;
    }
}

// ---------------- per-group stage loader (128 threads of group g) ----------------
static __device__ __forceinline__ void load_stage(
    uint32_t sb, int s, int m0, int n0, int kt, int g, int gtid)
{
    const uint32_t base = sb + (uint32_t)s * STAGE_BYTES + (uint32_t)g * GROUP_BYTES;
    const int kh = kt * BK;

    // A: own copy of the full 128-row A tile (8 chunks/thread)
    #pragma unroll
    for (int i = 0; i < (BM * 8) / 128; i++) {
        int c = gtid + i * 128;
        int row = c >> 3, seg = c & 7;
        uint32_t off = (uint32_t)row * 128 + (uint32_t)seg * 16;
        cp16(base + sw128(off), g_xh + (size_t)(m0 + row) * SZ_K + kh + seg * 8);
    }
    // B half: group's 128 columns (8 chunks/thread)
    const uint32_t bbase = base + GROUP_A_BYTES;
    const int bn0 = n0 + g * 128;
    #pragma unroll
    for (int i = 0; i < (128 * 8) / 128; i++) {
        int c = gtid + i * 128;
        int row = c >> 3, seg = c & 7;
        uint32_t off = (uint32_t)row * 128 + (uint32_t)seg * 16;
        cp16(bbase + sw128(off), g_wh + (size_t)(bn0 + row) * SZ_K + kh + seg * 8);
    }
}

// ---------------- persistent GEMM kernel (R15 mainloop + optional convert duty) --
// CVT=1 (round 0, tiles 0..147): each thread also streams 4 float4 of x per
// iteration through a 2-buffer smem staging ring: cp.async issued in the same
// commit group as the stage loads (arrival proven by the existing wait_group 1
// two iters later), then converted fp32->fp16 and stored to g_xh. Duty covers
// x chunks 10..63 and finishes by iter ~48 of 64. No consumer of these chunks
// exists inside this kernel; the kernel boundary orders them for gemm<0>.
// CVT=0: byte-identical R15 mainloop on tiles [tbase, tbase+tcnt).
template<int CVT>
__global__ void __launch_bounds__(NTHREADS, 1)
gemm_hmma_kernel(const float* __restrict__ gx,
                 const float* __restrict__ wscale,
                 const float* __restrict__ bias,
                 float* __restrict__ out,
                 int tbase, int tcnt)
{
    extern __shared__ char smem[];
    const uint32_t sb = smem_u32(smem);
    const int tid  = threadIdx.x;
    const int wid  = tid >> 5;
    const int lane = tid & 31;
    const int g    = wid >> 2;        // group 0/1
    const int w    = wid & 3;
    const int wm   = w & 1;
    const int wn   = w >> 1;
    const int gtid = tid & 127;
    const int bid  = blockIdx.x;
    const int gthr = bid * NTHREADS + tid;   // duty lane (CVT only)

    const int ntiles = (tcnt - 1 - bid) / GRID + 1;
    const int GJ = ntiles * KIT;

    const int l7   = lane & 7;
    const int hi8  = (lane >> 3) & 1;
    const int hi16 = lane >> 4;

    const int arow_base = wm * 64 + hi8 * 8 + l7;
    const int akb_base  = hi16 * 16;
    const int brow_base = wn * 64 + hi16 * 8 + l7;
    const int bkb_base  = hi8 * 16;

    float d[4][8][4];
    #pragma unroll
    for (int i = 0; i < 4; i++)
        #pragma unroll
        for (int j = 0; j < 8; j++)
            #pragma unroll
            for (int c = 0; c < 4; c++) d[i][j][c] = 0.0f;

    // incremental coordinates of the tile being LOADED (j+2 stream)
    int lt  = tbase + bid;
    int lkt = 0;
    int ln0 = (lt & (NTILE_N - 1)) * BN;
    int lm0 = (lt >> 4) * BM;

    load_stage(sb, 0, lm0, ln0, 0, g, gtid);
    asm volatile("cp.async.commit_group;" ::: "memory");
    load_stage(sb, 1, lm0, ln0, 1, g, gtid);
    asm volatile("cp.async.commit_group;" ::: "memory");
    lkt = 2;

    // incremental coordinates of the tile being COMPUTED / epilogued
    int et  = tbase + bid;
    int en0 = ln0, em0 = lm0;

    int s0 = 0;   // stage of j
    int s2 = 2;   // stage of j+2

    #pragma unroll 1
    for (int j = 0; j < GJ; j++) {
        if (j + 2 < GJ)
            asm volatile("cp.async.wait_group 1;" ::: "memory");
        else
            asm volatile("cp.async.wait_group 0;" ::: "memory");
        group_bar(g);   // stage j resident for this group

        // ---- duty consume: staging written at iter j-2 (group j-2 complete) ----
        if (CVT && j >= 2 && (j - 2) * DUTY < 188) {
            const int kb = (j - 2) * DUTY;
            const uint32_t buf = sb + STAGE_OFF + (uint32_t)(j & 1) * STAGE_BUF
                               + (uint32_t)tid * (DUTY * 16);
            #pragma unroll
            for (int r = 0; r < DUTY; r++) {
                size_t q = (size_t)(kb + r) * NTHRG + gthr;
                if (q < P2F4) {
                    float4 f;
                    asm volatile("ld.shared.v4.f32 {%0,%1,%2,%3}, [%4];"
                                 : "=f"(f.x), "=f"(f.y), "=f"(f.z), "=f"(f.w)
                                 : "r"(buf + r * 16));
                    __half2 h0 = __floats2half2_rn(f.x, f.y);
                    __half2 h1 = __floats2half2_rn(f.z, f.w);
                    uint2 o;
                    o.x = *reinterpret_cast<unsigned*>(&h0);
                    o.y = *reinterpret_cast<unsigned*>(&h1);
                    reinterpret_cast<uint2*>(g_xh)[P2BASE + q] = o;
                }
            }
        }

        if (j + 2 < GJ) {
            load_stage(sb, s2, lm0, ln0, lkt, g, gtid);
            // ---- duty issue: same commit group as the stage loads ----
            if (CVT && j * DUTY < 188) {
                const int kb = j * DUTY;
                const uint32_t buf = sb + STAGE_OFF + (uint32_t)(j & 1) * STAGE_BUF
                                   + (uint32_t)tid * (DUTY * 16);
                #pragma unroll
                for (int r = 0; r < DUTY; r++) {
                    size_t q = (size_t)(kb + r) * NTHRG + gthr;
                    if (q < P2F4)
                        cp16(buf + r * 16,
                             reinterpret_cast<const float4*>(gx) + P2BASE + q);
                }
            }
            asm volatile("cp.async.commit_group;" ::: "memory");
            if (++lkt == KIT) {
                lkt = 0;
                lt += GRID;
                ln0 = (lt & (NTILE_N - 1)) * BN;
                lm0 = (lt >> 4) * BM;
            }
        }

        const uint32_t abase = sb + (uint32_t)s0 * STAGE_BYTES + (uint32_t)g * GROUP_BYTES;
        const uint32_t bbase = abase + GROUP_A_BYTES;

        #pragma unroll
        for (int ks = 0; ks < BK / 16; ks++) {
            uint32_t a[4][4];
            #pragma unroll
            for (int mt = 0; mt < 4; mt++) {
                uint32_t off = (uint32_t)(arow_base + mt * 16) * 128
                             + (uint32_t)(ks * 32 + akb_base);
                ldm_x4(abase + sw128(off), a[mt][0], a[mt][1], a[mt][2], a[mt][3]);
            }
            uint32_t bfr[8][2];
            #pragma unroll
            for (int np = 0; np < 4; np++) {
                uint32_t off = (uint32_t)(brow_base + np * 16) * 128
                             + (uint32_t)(ks * 32 + bkb_base);
                uint32_t r0, r1, r2, r3;
                ldm_x4(bbase + sw128(off), r0, r1, r2, r3);
                bfr[np * 2 + 0][0] = r0; bfr[np * 2 + 0][1] = r1;
                bfr[np * 2 + 1][0] = r2; bfr[np * 2 + 1][1] = r3;
            }
            #pragma unroll
            for (int mt = 0; mt < 4; mt++)
                #pragma unroll
                for (int nt = 0; nt < 8; nt++)
                    mma16816(d[mt][nt][0], d[mt][nt][1], d[mt][nt][2], d[mt][nt][3],
                             a[mt][0], a[mt][1], a[mt][2], a[mt][3],
                             bfr[nt][0], bfr[nt][1]);
        }

        s0 = (s0 == 2) ? 0 : s0 + 1;
        s2 = (s2 == 2) ? 0 : s2 + 1;

        // ---------------- tile epilogue ----------------
        if ((j & (KIT - 1)) == KIT - 1) {
            const int crow = em0 + wm * 64 + (lane >> 2);
            const int ccol = en0 + g * 128 + wn * 64 + (lane & 3) * 2;

            float sc0[8], sc1[8], bi0[8], bi1[8];
            #pragma unroll
            for (int nt = 0; nt < 8; nt++) {
                sc0[nt] = __ldg(wscale + ccol + nt * 8);
                sc1[nt] = __ldg(wscale + ccol + nt * 8 + 1);
                bi0[nt] = __ldg(bias   + ccol + nt * 8);
                bi1[nt] = __ldg(bias   + ccol + nt * 8 + 1);
            }

            #pragma unroll
            for (int mt = 0; mt < 4; mt++) {
                #pragma unroll
                for (int nt = 0; nt < 8; nt++) {
                    float2 v0, v1;
                    v0.x = fmaf(d[mt][nt][0], sc0[nt], bi0[nt]);
                    v0.y = fmaf(d[mt][nt][1], sc1[nt], bi1[nt]);
                    v1.x = fmaf(d[mt][nt][2], sc0[nt], bi0[nt]);
                    v1.y = fmaf(d[mt][nt][3], sc1[nt], bi1[nt]);
                    size_t r0 = (size_t)(crow + mt * 16) * SZ_N + ccol + nt * 8;
                    size_t r1 = r0 + 8 * SZ_N;
                    *reinterpret_cast<float2*>(out + r0) = v0;
                    *reinterpret_cast<float2*>(out + r1) = v1;
                    d[mt][nt][0] = 0.0f; d[mt][nt][1] = 0.0f;
                    d[mt][nt][2] = 0.0f; d[mt][nt][3] = 0.0f;
                }
            }

            et += GRID;
            en0 = (et & (NTILE_N - 1)) * BN;
            em0 = (et >> 4) * BM;
        }
    }
}

// ---------------- launch ----------------
extern "C" void kernel_launch(void* const* d_in, const int* in_sizes, int n_in,
                              void* d_out, int out_size)
{
    const float* x  = (const float*)d_in[0];   // [4,2048,4096] fp32
    const int*   qw = (const int*)  d_in[1];   // [4096,4096] int32 in [-8,7]
    const float* ws = (const float*)d_in[2];   // [4096]
    const float* bs = (const float*)d_in[3];   // [4096]
    float* out = (float*)d_out;                // [4,2048,4096] fp32

    cudaFuncSetAttribute(gemm_hmma_kernel<1>,
                         cudaFuncAttributeMaxDynamicSharedMemorySize, SMEM_TOTAL);
    cudaFuncSetAttribute(gemm_hmma_kernel<0>,
                         cudaFuncAttributeMaxDynamicSharedMemorySize, SMEM_TOTAL);

    // phase 1: W + x chunks 0..9 (everything round 0 touches)
    cvt_phase1_kernel<<<(unsigned)((X10C8 + WC8) / 256), 256>>>(x, qw);

    // round 0 (tiles 0..147) + hidden conversion of x chunks 10..63
    gemm_hmma_kernel<1><<<GRID, NTHREADS, SMEM_TOTAL>>>(x, ws, bs, out, 0, GRID);

    // remaining tiles; kernel boundary orders all conversions before these reads
    gemm_hmma_kernel<0><<<GRID, NTHREADS, SMEM_TOTAL>>>(x, ws, bs, out,
                                                        GRID, NTILES - GRID);
}